// round 1
// baseline (speedup 1.0000x reference)
#include <cuda_runtime.h>
#include <cuda_bf16.h>
#include <cstdint>

#define BB 4
#define NUM_VN 65536
#define NUM_CN 32768
#define DD 32
#define EE 262144          // 2^18
#define HID 40
#define MSG 20

// scatter scratch: [2 sides][B][NUM_CN][MSG] — stays L2-resident (21 MB)
__device__ __align__(16) float g_msum[2][BB][NUM_CN][MSG];

// ---------------------------------------------------------------------------
// zero the scatter scratch (float4 stores)
// ---------------------------------------------------------------------------
__global__ void zero_kernel() {
    size_t i = (size_t)blockIdx.x * blockDim.x + threadIdx.x;
    const size_t n4 = (size_t)2 * BB * NUM_CN * MSG / 4;
    float4* p = reinterpret_cast<float4*>(&g_msum[0][0][0][0]);
    if (i < n4) p[i] = make_float4(0.f, 0.f, 0.f, 0.f);
}

// ---------------------------------------------------------------------------
// Edge MLP + scatter:  msg = relu([h_from[fi], h_to[ti]] @ Wm1) @ Wm2
//                      msum[b, ti, :] += msg   (vector red)
// one thread = one (b, e) edge instance
// ---------------------------------------------------------------------------
__global__ __launch_bounds__(256) void edge_kernel(
    const float* __restrict__ h_from,   // [B, NUM_VN, D]
    const float* __restrict__ h_to,     // [B, NUM_CN, D]
    const int*   __restrict__ from_ind, // [E]
    const int*   __restrict__ to_ind,   // [E]
    const float* __restrict__ Wm1,      // [2D, HID]
    const float* __restrict__ Wm2,      // [HID, MSG]
    float*       __restrict__ msum)     // [B, NUM_CN, MSG]
{
    // Wm1 transposed -> sW1[j][k] so k is contiguous (float4 loads)
    __shared__ float4 sW1[HID][16];     // [j][k/4], k in [0,64)
    __shared__ float4 sW2[HID][5];      // [j][m/4], m in [0,20)
    {
        float* s1 = reinterpret_cast<float*>(sW1);
        for (int i = threadIdx.x; i < 2 * DD * HID; i += 256) {
            int k = i / HID, j = i % HID;
            s1[j * 64 + k] = Wm1[i];
        }
        float* s2 = reinterpret_cast<float*>(sW2);
        for (int i = threadIdx.x; i < HID * MSG; i += 256)
            s2[i] = Wm2[i];
    }
    __syncthreads();

    int idx = blockIdx.x * 256 + threadIdx.x;   // [0, B*E)
    if (idx >= BB * EE) return;
    int e = idx & (EE - 1);
    int b = idx >> 18;

    int fi = from_ind[e];
    int ti = to_ind[e];

    float feat[64];
    {
        const float4* pf = reinterpret_cast<const float4*>(
            h_from + ((size_t)b * NUM_VN + fi) * DD);
        const float4* pt = reinterpret_cast<const float4*>(
            h_to + ((size_t)b * NUM_CN + ti) * DD);
        #pragma unroll
        for (int q = 0; q < 8; q++) {
            float4 v = pf[q];
            feat[4*q+0] = v.x; feat[4*q+1] = v.y; feat[4*q+2] = v.z; feat[4*q+3] = v.w;
        }
        #pragma unroll
        for (int q = 0; q < 8; q++) {
            float4 v = pt[q];
            feat[32+4*q+0] = v.x; feat[32+4*q+1] = v.y; feat[32+4*q+2] = v.z; feat[32+4*q+3] = v.w;
        }
    }

    float msg[MSG];
    #pragma unroll
    for (int m = 0; m < MSG; m++) msg[m] = 0.f;

    #pragma unroll 2
    for (int j = 0; j < HID; j++) {
        float h = 0.f;
        #pragma unroll
        for (int q = 0; q < 16; q++) {
            float4 w = sW1[j][q];
            h += feat[4*q+0] * w.x + feat[4*q+1] * w.y
               + feat[4*q+2] * w.z + feat[4*q+3] * w.w;
        }
        h = fmaxf(h, 0.f);
        #pragma unroll
        for (int q = 0; q < 5; q++) {
            float4 w = sW2[j][q];
            msg[4*q+0] += h * w.x; msg[4*q+1] += h * w.y;
            msg[4*q+2] += h * w.z; msg[4*q+3] += h * w.w;
        }
    }

    float* base = msum + ((size_t)b * NUM_CN + ti) * MSG;  // 80B rows, 16B aligned
    #pragma unroll
    for (int q = 0; q < 5; q++) {
        asm volatile("red.global.add.v4.f32 [%0], {%1, %2, %3, %4};"
                     :: "l"(base + 4 * q),
                        "f"(msg[4*q+0]), "f"(msg[4*q+1]),
                        "f"(msg[4*q+2]), "f"(msg[4*q+3])
                     : "memory");
    }
}

// ---------------------------------------------------------------------------
// Node MLP:  out = relu([m, h_to, logit] @ We1) @ We2
// one thread = one (b, cn) node
// ---------------------------------------------------------------------------
__global__ __launch_bounds__(256) void node_kernel(
    const float* __restrict__ msum,   // [B, NUM_CN, MSG]
    const float* __restrict__ h_to,   // [B, NUM_CN, D]
    const float* __restrict__ logit,  // [B, NUM_CN]
    const float* __restrict__ We1,    // [53, HID]
    const float* __restrict__ We2,    // [HID, D]
    float*       __restrict__ out)    // [B, NUM_CN, D]
{
    __shared__ float4 sE1[HID][14];   // transposed [j][k/4], k padded 53->56
    __shared__ float4 sE2[HID][8];    // [j][m/4], m in [0,32)
    {
        float* s1 = reinterpret_cast<float*>(sE1);
        for (int i = threadIdx.x; i < HID * 56; i += 256) {
            int j = i / 56, k = i % 56;
            s1[i] = (k < MSG + DD + 1) ? We1[k * HID + j] : 0.f;
        }
        float* s2 = reinterpret_cast<float*>(sE2);
        for (int i = threadIdx.x; i < HID * DD; i += 256)
            s2[i] = We2[i];
    }
    __syncthreads();

    int idx = blockIdx.x * 256 + threadIdx.x;   // [0, B*NUM_CN)
    if (idx >= BB * NUM_CN) return;

    float ein[56];
    {
        const float4* pm = reinterpret_cast<const float4*>(msum + (size_t)idx * MSG);
        #pragma unroll
        for (int q = 0; q < 5; q++) {
            float4 v = pm[q];
            ein[4*q+0] = v.x; ein[4*q+1] = v.y; ein[4*q+2] = v.z; ein[4*q+3] = v.w;
        }
        const float4* ph = reinterpret_cast<const float4*>(h_to + (size_t)idx * DD);
        #pragma unroll
        for (int q = 0; q < 8; q++) {
            float4 v = ph[q];
            ein[20+4*q+0] = v.x; ein[20+4*q+1] = v.y;
            ein[20+4*q+2] = v.z; ein[20+4*q+3] = v.w;
        }
        ein[52] = logit[idx];
        ein[53] = 0.f; ein[54] = 0.f; ein[55] = 0.f;
    }

    float acc[DD];
    #pragma unroll
    for (int m = 0; m < DD; m++) acc[m] = 0.f;

    #pragma unroll 2
    for (int j = 0; j < HID; j++) {
        float h = 0.f;
        #pragma unroll
        for (int q = 0; q < 14; q++) {
            float4 w = sE1[j][q];
            h += ein[4*q+0] * w.x + ein[4*q+1] * w.y
               + ein[4*q+2] * w.z + ein[4*q+3] * w.w;
        }
        h = fmaxf(h, 0.f);
        #pragma unroll
        for (int q = 0; q < 8; q++) {
            float4 w = sE2[j][q];
            acc[4*q+0] += h * w.x; acc[4*q+1] += h * w.y;
            acc[4*q+2] += h * w.z; acc[4*q+3] += h * w.w;
        }
    }

    float4* po = reinterpret_cast<float4*>(out + (size_t)idx * DD);
    #pragma unroll
    for (int q = 0; q < 8; q++)
        po[q] = make_float4(acc[4*q+0], acc[4*q+1], acc[4*q+2], acc[4*q+3]);
}

// ---------------------------------------------------------------------------
extern "C" void kernel_launch(void* const* d_in, const int* in_sizes, int n_in,
                              void* d_out, int out_size) {
    const float* h_from     = (const float*)d_in[0];
    const float* h_to_x     = (const float*)d_in[1];
    const float* h_to_z     = (const float*)d_in[2];
    const float* hx_logit   = (const float*)d_in[3];
    const float* hz_logit   = (const float*)d_in[4];
    const int*   from_ind_x = (const int*)  d_in[5];
    const int*   to_ind_x   = (const int*)  d_in[6];
    const int*   from_ind_z = (const int*)  d_in[7];
    const int*   to_ind_z   = (const int*)  d_in[8];
    const float* Wm1_x      = (const float*)d_in[9];
    const float* Wm2_x      = (const float*)d_in[10];
    const float* Wm1_z      = (const float*)d_in[11];
    const float* Wm2_z      = (const float*)d_in[12];
    const float* We1_x      = (const float*)d_in[13];
    const float* We2_x      = (const float*)d_in[14];
    const float* We1_z      = (const float*)d_in[15];
    const float* We2_z      = (const float*)d_in[16];
    float* out = (float*)d_out;

    float* msum = nullptr;
    cudaGetSymbolAddress((void**)&msum, g_msum);
    float* msum_x = msum;
    float* msum_z = msum + (size_t)BB * NUM_CN * MSG;

    // zero scratch
    {
        const size_t n4 = (size_t)2 * BB * NUM_CN * MSG / 4;
        int blocks = (int)((n4 + 255) / 256);
        zero_kernel<<<blocks, 256>>>();
    }

    // edge MLP + scatter (x, then z)
    {
        int blocks = (BB * EE) / 256;
        edge_kernel<<<blocks, 256>>>(h_from, h_to_x, from_ind_x, to_ind_x,
                                     Wm1_x, Wm2_x, msum_x);
        edge_kernel<<<blocks, 256>>>(h_from, h_to_z, from_ind_z, to_ind_z,
                                     Wm1_z, Wm2_z, msum_z);
    }

    // node MLP -> output
    {
        int blocks = (BB * NUM_CN) / 256;
        node_kernel<<<blocks, 256>>>(msum_x, h_to_x, hx_logit, We1_x, We2_x,
                                     out);
        node_kernel<<<blocks, 256>>>(msum_z, h_to_z, hz_logit, We1_z, We2_z,
                                     out + (size_t)BB * NUM_CN * DD);
    }
}

// round 3
// speedup vs baseline: 1.5830x; 1.5830x over previous
#include <cuda_runtime.h>
#include <cuda_bf16.h>
#include <cstdint>

#define BB 4
#define NUM_VN 65536
#define NUM_CN 32768
#define DD 32
#define EE 262144          // 2^18
#define HID 40
#define MSG 20

typedef unsigned long long ull;

// ---- packed fp32x2 helpers (sm_100+) --------------------------------------
__device__ __forceinline__ ull fpack(float a, float b) {
    ull r; asm("mov.b64 %0, {%1,%2};" : "=l"(r) : "f"(a), "f"(b)); return r;
}
__device__ __forceinline__ void funpack(ull v, float& a, float& b) {
    asm("mov.b64 {%0,%1}, %2;" : "=f"(a), "=f"(b) : "l"(v));
}
__device__ __forceinline__ ull ffma2(ull a, ull b, ull c) {
    ull r; asm("fma.rn.f32x2 %0, %1, %2, %3;" : "=l"(r) : "l"(a), "l"(b), "l"(c));
    return r;
}
__device__ __forceinline__ ull fadd2(ull a, ull b) {
    ull r; asm("add.rn.f32x2 %0, %1, %2;" : "=l"(r) : "l"(a), "l"(b)); return r;
}

union F4P { float4 v; ull p[2]; };

// ---- device scratch (single-side, reused across sides) --------------------
// F[b*NUM_VN + vn][HID]  : h_from @ Wm1[0:32]     42 MB
// T[b*NUM_CN + cn][HID]  : h_to   @ Wm1[32:64]    21 MB
// msum[b*NUM_CN + cn][MSG]                        10.5 MB
__device__ __align__(16) float g_F[(size_t)BB * NUM_VN * HID];
__device__ __align__(16) float g_T[(size_t)BB * NUM_CN * HID];
__device__ __align__(16) float g_msum[(size_t)BB * NUM_CN * MSG];

// ---------------------------------------------------------------------------
__global__ void zero_kernel(float4* __restrict__ p, int n4) {
    int i = blockIdx.x * blockDim.x + threadIdx.x;
    if (i < n4) p[i] = make_float4(0.f, 0.f, 0.f, 0.f);
}

// ---------------------------------------------------------------------------
// P[n, :] = h[n, 0:32] @ W (W = 32xHID sub-block of Wm1, row-major stride HID)
// one thread per node instance
// ---------------------------------------------------------------------------
__global__ __launch_bounds__(256) void pre_kernel(
    const float* __restrict__ h,   // [N, 32]
    const float* __restrict__ W,   // rows [0,32) of some [.., HID] block
    float*       __restrict__ P,   // [N, HID]
    int N)
{
    __shared__ float sW[HID][32];  // transposed: sW[j][k] = W[k][j]
    for (int i = threadIdx.x; i < 32 * HID; i += 256) {
        int k = i / HID, j = i % HID;
        sW[j][k] = W[i];
    }
    __syncthreads();

    int idx = blockIdx.x * 256 + threadIdx.x;
    if (idx >= N) return;

    ull xp[16];
    {
        const float4* p4 = reinterpret_cast<const float4*>(h + (size_t)idx * DD);
        #pragma unroll
        for (int q = 0; q < 8; q++) {
            F4P u; u.v = p4[q];
            xp[2*q] = u.p[0]; xp[2*q+1] = u.p[1];
        }
    }

    float out[HID];
    #pragma unroll 4
    for (int j = 0; j < HID; j++) {
        const float4* w4 = reinterpret_cast<const float4*>(sW[j]);
        ull a0 = 0ull, a1 = 0ull;
        #pragma unroll
        for (int q = 0; q < 8; q++) {
            F4P w; w.v = w4[q];
            a0 = ffma2(xp[2*q],   w.p[0], a0);
            a1 = ffma2(xp[2*q+1], w.p[1], a1);
        }
        float x0, x1, y0, y1;
        funpack(a0, x0, x1); funpack(a1, y0, y1);
        out[j] = (x0 + y0) + (x1 + y1);
    }

    float4* po = reinterpret_cast<float4*>(P + (size_t)idx * HID);
    #pragma unroll
    for (int q = 0; q < 10; q++)
        po[q] = make_float4(out[4*q], out[4*q+1], out[4*q+2], out[4*q+3]);
}

// ---------------------------------------------------------------------------
// Edge: h = relu(F[fi] + T[ti]);  msg = h @ Wm2;  msum[b,ti,:] += msg
// one thread per (b, e) edge instance
// ---------------------------------------------------------------------------
__global__ __launch_bounds__(256) void edge_kernel(
    const float* __restrict__ F,        // [B*NUM_VN, HID]
    const float* __restrict__ T,        // [B*NUM_CN, HID]
    const int*   __restrict__ from_ind, // [E]
    const int*   __restrict__ to_ind,   // [E]
    const float* __restrict__ Wm2,      // [HID, MSG]
    float*       __restrict__ msum)     // [B, NUM_CN, MSG]
{
    __shared__ float sW2[HID][MSG];     // rows of 80B, 16B aligned
    for (int i = threadIdx.x; i < HID * MSG; i += 256)
        (&sW2[0][0])[i] = Wm2[i];
    __syncthreads();

    int idx = blockIdx.x * 256 + threadIdx.x;   // [0, B*E)
    int e = idx & (EE - 1);
    int b = idx >> 18;

    int fi = from_ind[e];
    int ti = to_ind[e];

    const float4* pf = reinterpret_cast<const float4*>(
        F + ((size_t)b * NUM_VN + fi) * HID);
    const float4* pt = reinterpret_cast<const float4*>(
        T + ((size_t)b * NUM_CN + ti) * HID);

    float h[HID];
    #pragma unroll
    for (int q = 0; q < 10; q++) {
        F4P a, c; a.v = pf[q]; c.v = pt[q];
        ull s0 = fadd2(a.p[0], c.p[0]);
        ull s1 = fadd2(a.p[1], c.p[1]);
        float t0, t1, t2, t3;
        funpack(s0, t0, t1); funpack(s1, t2, t3);
        h[4*q]   = fmaxf(t0, 0.f);
        h[4*q+1] = fmaxf(t1, 0.f);
        h[4*q+2] = fmaxf(t2, 0.f);
        h[4*q+3] = fmaxf(t3, 0.f);
    }

    ull msg[10];
    #pragma unroll
    for (int q = 0; q < 10; q++) msg[q] = 0ull;

    #pragma unroll 8
    for (int j = 0; j < HID; j++) {
        ull hh = fpack(h[j], h[j]);
        const float4* w4 = reinterpret_cast<const float4*>(sW2[j]);
        #pragma unroll
        for (int q = 0; q < 5; q++) {
            F4P w; w.v = w4[q];
            msg[2*q]   = ffma2(hh, w.p[0], msg[2*q]);
            msg[2*q+1] = ffma2(hh, w.p[1], msg[2*q+1]);
        }
    }

    float m[MSG];
    #pragma unroll
    for (int q = 0; q < 10; q++) funpack(msg[q], m[2*q], m[2*q+1]);

    float* base = msum + ((size_t)b * NUM_CN + ti) * MSG;
    #pragma unroll
    for (int q = 0; q < 5; q++) {
        asm volatile("red.global.add.v4.f32 [%0], {%1, %2, %3, %4};"
                     :: "l"(base + 4 * q),
                        "f"(m[4*q]), "f"(m[4*q+1]), "f"(m[4*q+2]), "f"(m[4*q+3])
                     : "memory");
    }
}

// ---------------------------------------------------------------------------
// Node: out = relu([m, h_to, logit] @ We1) @ We2
// one thread per (b, cn) node
// ---------------------------------------------------------------------------
__global__ __launch_bounds__(256) void node_kernel(
    const float* __restrict__ msum,   // [B*NUM_CN, MSG]
    const float* __restrict__ h_to,   // [B*NUM_CN, D]
    const float* __restrict__ logit,  // [B*NUM_CN]
    const float* __restrict__ We1,    // [53, HID]
    const float* __restrict__ We2,    // [HID, D]
    float*       __restrict__ out)    // [B*NUM_CN, D]
{
    __shared__ float sE1[HID][56];    // transposed, padded 53->56, zeros in pad
    __shared__ float sE2[HID][DD];
    {
        for (int i = threadIdx.x; i < HID * 56; i += 256) {
            int j = i / 56, k = i % 56;
            sE1[j][k] = (k < MSG + DD + 1) ? We1[k * HID + j] : 0.f;
        }
        for (int i = threadIdx.x; i < HID * DD; i += 256)
            (&sE2[0][0])[i] = We2[i];
    }
    __syncthreads();

    int idx = blockIdx.x * 256 + threadIdx.x;   // [0, B*NUM_CN)

    ull ein[28];
    {
        const float4* pm = reinterpret_cast<const float4*>(msum + (size_t)idx * MSG);
        #pragma unroll
        for (int q = 0; q < 5; q++) {
            F4P u; u.v = pm[q];
            ein[2*q] = u.p[0]; ein[2*q+1] = u.p[1];
        }
        const float4* ph = reinterpret_cast<const float4*>(h_to + (size_t)idx * DD);
        #pragma unroll
        for (int q = 0; q < 8; q++) {
            F4P u; u.v = ph[q];
            ein[10+2*q] = u.p[0]; ein[10+2*q+1] = u.p[1];
        }
        ein[26] = fpack(logit[idx], 0.f);
        ein[27] = 0ull;
    }

    ull acc[16];
    #pragma unroll
    for (int q = 0; q < 16; q++) acc[q] = 0ull;

    #pragma unroll 4
    for (int j = 0; j < HID; j++) {
        const float4* w4 = reinterpret_cast<const float4*>(sE1[j]);
        ull a0 = 0ull, a1 = 0ull;
        #pragma unroll
        for (int q = 0; q < 14; q++) {
            F4P w; w.v = w4[q];
            a0 = ffma2(ein[2*q],   w.p[0], a0);
            a1 = ffma2(ein[2*q+1], w.p[1], a1);
        }
        float x0, x1, y0, y1;
        funpack(a0, x0, x1); funpack(a1, y0, y1);
        float hv = fmaxf((x0 + y0) + (x1 + y1), 0.f);
        ull hh = fpack(hv, hv);

        const float4* v4 = reinterpret_cast<const float4*>(sE2[j]);
        #pragma unroll
        for (int q = 0; q < 8; q++) {
            F4P w; w.v = v4[q];
            acc[2*q]   = ffma2(hh, w.p[0], acc[2*q]);
            acc[2*q+1] = ffma2(hh, w.p[1], acc[2*q+1]);
        }
    }

    float o[DD];
    #pragma unroll
    for (int q = 0; q < 16; q++) funpack(acc[q], o[2*q], o[2*q+1]);
    float4* po = reinterpret_cast<float4*>(out + (size_t)idx * DD);
    #pragma unroll
    for (int q = 0; q < 8; q++)
        po[q] = make_float4(o[4*q], o[4*q+1], o[4*q+2], o[4*q+3]);
}

// ---------------------------------------------------------------------------
static void run_side(const float* h_from, const float* h_to,
                     const float* logit,
                     const int* from_ind, const int* to_ind,
                     const float* Wm1, const float* Wm2,
                     const float* We1, const float* We2,
                     float* F, float* T, float* M, float* out)
{
    const int Nf = BB * NUM_VN;   // 262144
    const int Nt = BB * NUM_CN;   // 131072

    // zero scatter scratch for this side
    {
        const int n4 = (int)((size_t)BB * NUM_CN * MSG / 4);
        zero_kernel<<<(n4 + 255) / 256, 256>>>(
            reinterpret_cast<float4*>(M), n4);
    }
    pre_kernel<<<Nf / 256, 256>>>(h_from, Wm1, F, Nf);
    pre_kernel<<<Nt / 256, 256>>>(h_to, Wm1 + 32 * HID, T, Nt);

    edge_kernel<<<(BB * EE) / 256, 256>>>(F, T, from_ind, to_ind, Wm2, M);

    node_kernel<<<Nt / 256, 256>>>(M, h_to, logit, We1, We2, out);
}

extern "C" void kernel_launch(void* const* d_in, const int* in_sizes, int n_in,
                              void* d_out, int out_size) {
    const float* h_from     = (const float*)d_in[0];
    const float* h_to_x     = (const float*)d_in[1];
    const float* h_to_z     = (const float*)d_in[2];
    const float* hx_logit   = (const float*)d_in[3];
    const float* hz_logit   = (const float*)d_in[4];
    const int*   from_ind_x = (const int*)  d_in[5];
    const int*   to_ind_x   = (const int*)  d_in[6];
    const int*   from_ind_z = (const int*)  d_in[7];
    const int*   to_ind_z   = (const int*)  d_in[8];
    const float* Wm1_x      = (const float*)d_in[9];
    const float* Wm2_x      = (const float*)d_in[10];
    const float* Wm1_z      = (const float*)d_in[11];
    const float* Wm2_z      = (const float*)d_in[12];
    const float* We1_x      = (const float*)d_in[13];
    const float* We2_x      = (const float*)d_in[14];
    const float* We1_z      = (const float*)d_in[15];
    const float* We2_z      = (const float*)d_in[16];
    float* out = (float*)d_out;

    float *F = nullptr, *T = nullptr, *M = nullptr;
    cudaGetSymbolAddress((void**)&F, g_F);
    cudaGetSymbolAddress((void**)&T, g_T);
    cudaGetSymbolAddress((void**)&M, g_msum);

    run_side(h_from, h_to_x, hx_logit, from_ind_x, to_ind_x,
             Wm1_x, Wm2_x, We1_x, We2_x, F, T, M, out);
    run_side(h_from, h_to_z, hz_logit, from_ind_z, to_ind_z,
             Wm1_z, Wm2_z, We1_z, We2_z, F, T, M,
             out + (size_t)BB * NUM_CN * DD);
}

// round 5
// speedup vs baseline: 1.9154x; 1.2099x over previous
#include <cuda_runtime.h>
#include <cuda_bf16.h>
#include <cuda_fp16.h>
#include <cstdint>

#define BB 4
#define NUM_VN 65536
#define NUM_CN 32768
#define DD 32
#define EE 262144          // 2^18
#define HID 40
#define MSG 20

typedef unsigned long long ull;

// ---- packed fp32x2 helpers (sm_100+) --------------------------------------
__device__ __forceinline__ ull fpack(float a, float b) {
    ull r; asm("mov.b64 %0, {%1,%2};" : "=l"(r) : "f"(a), "f"(b)); return r;
}
__device__ __forceinline__ void funpack(ull v, float& a, float& b) {
    asm("mov.b64 {%0,%1}, %2;" : "=f"(a), "=f"(b) : "l"(v));
}
__device__ __forceinline__ ull ffma2(ull a, ull b, ull c) {
    ull r; asm("fma.rn.f32x2 %0, %1, %2, %3;" : "=l"(r) : "l"(a), "l"(b), "l"(c));
    return r;
}

union F4P { float4 v; ull p[2]; };
union U4H { uint4 v; __half2 h[4]; };

// ---- device scratch (single side, reused across sides) --------------------
// Fh[b*NUM_VN + vn][HID]  : fp16,  21 MB
// Th[b*NUM_CN + cn][HID]  : fp16,  10.5 MB
// msum[b*NUM_CN+cn][MSG]  : fp32,  10.5 MB        total 42 MB
__device__ __align__(16) __half g_Fh[(size_t)BB * NUM_VN * HID];
__device__ __align__(16) __half g_Th[(size_t)BB * NUM_CN * HID];
__device__ __align__(16) float  g_msum[(size_t)BB * NUM_CN * MSG];

// ---------------------------------------------------------------------------
__global__ void zero_kernel(float4* __restrict__ p, int n4) {
    int i = blockIdx.x * blockDim.x + threadIdx.x;
    if (i < n4) p[i] = make_float4(0.f, 0.f, 0.f, 0.f);
}

// ---------------------------------------------------------------------------
// P[n,:] = fp16( h[n,0:32] @ W ), W = 32xHID sub-block of Wm1 (stride HID)
// one thread per node instance
// ---------------------------------------------------------------------------
__global__ __launch_bounds__(256) void pre_kernel(
    const float* __restrict__ h,   // [N, 32]
    const float* __restrict__ W,   // [32, HID]
    __half*      __restrict__ P,   // [N, HID] fp16
    int N)
{
    __shared__ float sW[HID][32];  // transposed: sW[j][k] = W[k][j]
    for (int i = threadIdx.x; i < 32 * HID; i += 256) {
        int k = i / HID, j = i % HID;
        sW[j][k] = W[i];
    }
    __syncthreads();

    int idx = blockIdx.x * 256 + threadIdx.x;
    if (idx >= N) return;

    ull xp[16];
    {
        const float4* p4 = reinterpret_cast<const float4*>(h + (size_t)idx * DD);
        #pragma unroll
        for (int q = 0; q < 8; q++) {
            F4P u; u.v = p4[q];
            xp[2*q] = u.p[0]; xp[2*q+1] = u.p[1];
        }
    }

    float out[HID];
    #pragma unroll 4
    for (int j = 0; j < HID; j++) {
        const float4* w4 = reinterpret_cast<const float4*>(sW[j]);
        ull a0 = 0ull, a1 = 0ull;
        #pragma unroll
        for (int q = 0; q < 8; q++) {
            F4P w; w.v = w4[q];
            a0 = ffma2(xp[2*q],   w.p[0], a0);
            a1 = ffma2(xp[2*q+1], w.p[1], a1);
        }
        float x0, x1, y0, y1;
        funpack(a0, x0, x1); funpack(a1, y0, y1);
        out[j] = (x0 + y0) + (x1 + y1);
    }

    uint4* po = reinterpret_cast<uint4*>(P + (size_t)idx * HID);
    #pragma unroll
    for (int q = 0; q < 5; q++) {
        U4H u;
        #pragma unroll
        for (int k = 0; k < 4; k++)
            u.h[k] = __float22half2_rn(
                make_float2(out[q*8 + 2*k], out[q*8 + 2*k + 1]));
        po[q] = u.v;
    }
}

// ---------------------------------------------------------------------------
// Edge: h = relu(F[fi] + T[ti]) (fp16); msg = h @ Wm2 (fp32 accum);
//       msum[b,ti,:] += msg (vector red)
// one thread per (b, e) edge instance
// ---------------------------------------------------------------------------
__global__ __launch_bounds__(256) void edge_kernel(
    const __half* __restrict__ F,        // [B*NUM_VN, HID] fp16
    const __half* __restrict__ T,        // [B*NUM_CN, HID] fp16
    const int*    __restrict__ from_ind, // [E]
    const int*    __restrict__ to_ind,   // [E]
    const float*  __restrict__ Wm2,      // [HID, MSG]
    float*        __restrict__ msum)     // [B*NUM_CN, MSG]
{
    __shared__ float sW2[HID][MSG];      // 80B rows, 16B aligned
    for (int i = threadIdx.x; i < HID * MSG; i += 256)
        (&sW2[0][0])[i] = Wm2[i];
    __syncthreads();

    int idx = blockIdx.x * 256 + threadIdx.x;   // [0, B*E)
    int e = idx & (EE - 1);
    int b = idx >> 18;

    int fi = from_ind[e];
    int ti = to_ind[e];

    const uint4* pf = reinterpret_cast<const uint4*>(
        F + ((size_t)b * NUM_VN + fi) * HID);
    const uint4* pt = reinterpret_cast<const uint4*>(
        T + ((size_t)b * NUM_CN + ti) * HID);

    U4H fa[5], ta[5];
    #pragma unroll
    for (int q = 0; q < 5; q++) fa[q].v = pf[q];
    #pragma unroll
    for (int q = 0; q < 5; q++) ta[q].v = pt[q];

    __half2 h2[20];
    const __half2 z2 = __float2half2_rn(0.f);
    #pragma unroll
    for (int q = 0; q < 5; q++)
        #pragma unroll
        for (int k = 0; k < 4; k++)
            h2[q*4 + k] = __hmax2(__hadd2(fa[q].h[k], ta[q].h[k]), z2);

    ull msg[10];
    #pragma unroll
    for (int q = 0; q < 10; q++) msg[q] = 0ull;

    #pragma unroll 5
    for (int p = 0; p < 20; p++) {
        float2 hf = __half22float2(h2[p]);
        ull h0 = fpack(hf.x, hf.x);
        ull h1 = fpack(hf.y, hf.y);
        const float4* w0 = reinterpret_cast<const float4*>(sW2[2*p]);
        const float4* w1 = reinterpret_cast<const float4*>(sW2[2*p + 1]);
        #pragma unroll
        for (int q = 0; q < 5; q++) {
            F4P a; a.v = w0[q];
            F4P c; c.v = w1[q];
            msg[2*q]   = ffma2(h0, a.p[0], msg[2*q]);
            msg[2*q+1] = ffma2(h0, a.p[1], msg[2*q+1]);
            msg[2*q]   = ffma2(h1, c.p[0], msg[2*q]);
            msg[2*q+1] = ffma2(h1, c.p[1], msg[2*q+1]);
        }
    }

    float m[MSG];
    #pragma unroll
    for (int q = 0; q < 10; q++) funpack(msg[q], m[2*q], m[2*q+1]);

    float* base = msum + ((size_t)b * NUM_CN + ti) * MSG;
    #pragma unroll
    for (int q = 0; q < 5; q++) {
        asm volatile("red.global.add.v4.f32 [%0], {%1, %2, %3, %4};"
                     :: "l"(base + 4 * q),
                        "f"(m[4*q]), "f"(m[4*q+1]), "f"(m[4*q+2]), "f"(m[4*q+3])
                     : "memory");
    }
}

// ---------------------------------------------------------------------------
// Node: out = relu([m, h_to, logit] @ We1) @ We2
// one thread per (b, cn) node
// ---------------------------------------------------------------------------
__global__ __launch_bounds__(256) void node_kernel(
    const float* __restrict__ msum,   // [B*NUM_CN, MSG]
    const float* __restrict__ h_to,   // [B*NUM_CN, D]
    const float* __restrict__ logit,  // [B*NUM_CN]
    const float* __restrict__ We1,    // [53, HID]
    const float* __restrict__ We2,    // [HID, D]
    float*       __restrict__ out)    // [B*NUM_CN, D]
{
    __shared__ float sE1[HID][56];    // transposed, padded 53->56
    __shared__ float sE2[HID][DD];
    {
        for (int i = threadIdx.x; i < HID * 56; i += 256) {
            int j = i / 56, k = i % 56;
            sE1[j][k] = (k < MSG + DD + 1) ? We1[k * HID + j] : 0.f;
        }
        for (int i = threadIdx.x; i < HID * DD; i += 256)
            (&sE2[0][0])[i] = We2[i];
    }
    __syncthreads();

    int idx = blockIdx.x * 256 + threadIdx.x;   // [0, B*NUM_CN)

    ull ein[28];
    {
        const float4* pm = reinterpret_cast<const float4*>(msum + (size_t)idx * MSG);
        #pragma unroll
        for (int q = 0; q < 5; q++) {
            F4P u; u.v = pm[q];
            ein[2*q] = u.p[0]; ein[2*q+1] = u.p[1];
        }
        const float4* ph = reinterpret_cast<const float4*>(h_to + (size_t)idx * DD);
        #pragma unroll
        for (int q = 0; q < 8; q++) {
            F4P u; u.v = ph[q];
            ein[10+2*q] = u.p[0]; ein[10+2*q+1] = u.p[1];
        }
        ein[26] = fpack(logit[idx], 0.f);
        ein[27] = 0ull;
    }

    ull acc[16];
    #pragma unroll
    for (int q = 0; q < 16; q++) acc[q] = 0ull;

    #pragma unroll 4
    for (int j = 0; j < HID; j++) {
        const float4* w4 = reinterpret_cast<const float4*>(sE1[j]);
        ull a0 = 0ull, a1 = 0ull;
        #pragma unroll
        for (int q = 0; q < 14; q++) {
            F4P w; w.v = w4[q];
            a0 = ffma2(ein[2*q],   w.p[0], a0);
            a1 = ffma2(ein[2*q+1], w.p[1], a1);
        }
        float x0, x1, y0, y1;
        funpack(a0, x0, x1); funpack(a1, y0, y1);
        float hv = fmaxf((x0 + y0) + (x1 + y1), 0.f);
        ull hh = fpack(hv, hv);

        const float4* v4 = reinterpret_cast<const float4*>(sE2[j]);
        #pragma unroll
        for (int q = 0; q < 8; q++) {
            F4P w; w.v = v4[q];
            acc[2*q]   = ffma2(hh, w.p[0], acc[2*q]);
            acc[2*q+1] = ffma2(hh, w.p[1], acc[2*q+1]);
        }
    }

    float o[DD];
    #pragma unroll
    for (int q = 0; q < 16; q++) funpack(acc[q], o[2*q], o[2*q+1]);
    float4* po = reinterpret_cast<float4*>(out + (size_t)idx * DD);
    #pragma unroll
    for (int q = 0; q < 8; q++)
        po[q] = make_float4(o[4*q], o[4*q+1], o[4*q+2], o[4*q+3]);
}

// ---------------------------------------------------------------------------
static void run_side(const float* h_from, const float* h_to,
                     const float* logit,
                     const int* from_ind, const int* to_ind,
                     const float* Wm1, const float* Wm2,
                     const float* We1, const float* We2,
                     __half* F, __half* T, float* M, float* out)
{
    const int Nf = BB * NUM_VN;   // 262144
    const int Nt = BB * NUM_CN;   // 131072

    {
        const int n4 = (int)((size_t)BB * NUM_CN * MSG / 4);
        zero_kernel<<<(n4 + 255) / 256, 256>>>(
            reinterpret_cast<float4*>(M), n4);
    }
    pre_kernel<<<Nf / 256, 256>>>(h_from, Wm1, F, Nf);
    pre_kernel<<<Nt / 256, 256>>>(h_to, Wm1 + 32 * HID, T, Nt);

    edge_kernel<<<(BB * EE) / 256, 256>>>(F, T, from_ind, to_ind, Wm2, M);

    node_kernel<<<Nt / 256, 256>>>(M, h_to, logit, We1, We2, out);
}

extern "C" void kernel_launch(void* const* d_in, const int* in_sizes, int n_in,
                              void* d_out, int out_size) {
    const float* h_from     = (const float*)d_in[0];
    const float* h_to_x     = (const float*)d_in[1];
    const float* h_to_z     = (const float*)d_in[2];
    const float* hx_logit   = (const float*)d_in[3];
    const float* hz_logit   = (const float*)d_in[4];
    const int*   from_ind_x = (const int*)  d_in[5];
    const int*   to_ind_x   = (const int*)  d_in[6];
    const int*   from_ind_z = (const int*)  d_in[7];
    const int*   to_ind_z   = (const int*)  d_in[8];
    const float* Wm1_x      = (const float*)d_in[9];
    const float* Wm2_x      = (const float*)d_in[10];
    const float* Wm1_z      = (const float*)d_in[11];
    const float* Wm2_z      = (const float*)d_in[12];
    const float* We1_x      = (const float*)d_in[13];
    const float* We2_x      = (const float*)d_in[14];
    const float* We1_z      = (const float*)d_in[15];
    const float* We2_z      = (const float*)d_in[16];
    float* out = (float*)d_out;

    __half *F = nullptr, *T = nullptr;
    float* M = nullptr;
    cudaGetSymbolAddress((void**)&F, g_Fh);
    cudaGetSymbolAddress((void**)&T, g_Th);
    cudaGetSymbolAddress((void**)&M, g_msum);

    run_side(h_from, h_to_x, hx_logit, from_ind_x, to_ind_x,
             Wm1_x, Wm2_x, We1_x, We2_x, F, T, M, out);
    run_side(h_from, h_to_z, hz_logit, from_ind_z, to_ind_z,
             Wm1_z, Wm2_z, We1_z, We2_z, F, T, M,
             out + (size_t)BB * NUM_CN * DD);
}

// round 7
// speedup vs baseline: 2.2171x; 1.1575x over previous
#include <cuda_runtime.h>
#include <cuda_bf16.h>
#include <cuda_fp16.h>
#include <cstdint>

#define BB 4
#define NUM_VN 65536
#define NUM_CN 32768
#define DD 32
#define EE 262144          // 2^18
#define HID 40
#define MSG 20

typedef unsigned long long ull;

// ---- packed fp32x2 helpers (sm_100+) --------------------------------------
__device__ __forceinline__ ull fpack(float a, float b) {
    ull r; asm("mov.b64 %0, {%1,%2};" : "=l"(r) : "f"(a), "f"(b)); return r;
}
__device__ __forceinline__ void funpack(ull v, float& a, float& b) {
    asm("mov.b64 {%0,%1}, %2;" : "=f"(a), "=f"(b) : "l"(v));
}
__device__ __forceinline__ ull ffma2(ull a, ull b, ull c) {
    ull r; asm("fma.rn.f32x2 %0, %1, %2, %3;" : "=l"(r) : "l"(a), "l"(b), "l"(c));
    return r;
}

union F4P { float4 v; ull p[2]; };
union U4H { uint4 v; __half2 h[4]; unsigned int u[4]; };

// ---- device scratch (single side, reused across sides) --------------------
// Fh   [b*NUM_VN + vn][HID] fp16 : 21   MB
// Th   [b*NUM_CN + cn][HID] fp16 : 10.5 MB
// hsum [b*NUM_CN + cn][HID] fp16 : 10.5 MB   (aggregated relu(F+T))
// m    [b*NUM_CN + cn][MSG] fp32 : 10.5 MB   (= hsum @ Wm2)
__device__ __align__(16) __half g_Fh[(size_t)BB * NUM_VN * HID];
__device__ __align__(16) __half g_Th[(size_t)BB * NUM_CN * HID];
__device__ __align__(16) __half g_hsum[(size_t)BB * NUM_CN * HID];
__device__ __align__(16) float  g_m[(size_t)BB * NUM_CN * MSG];

// ---------------------------------------------------------------------------
__global__ void zero_kernel(uint4* __restrict__ p, int n) {
    int i = blockIdx.x * blockDim.x + threadIdx.x;
    if (i < n) p[i] = make_uint4(0u, 0u, 0u, 0u);
}

// ---------------------------------------------------------------------------
// P[n,:] = fp16( h[n,0:32] @ W ), W = [32, HID] sub-block of Wm1 (stride HID)
// ---------------------------------------------------------------------------
__global__ __launch_bounds__(256) void pre_kernel(
    const float* __restrict__ h,   // [N, 32]
    const float* __restrict__ W,   // [32, HID]
    __half*      __restrict__ P,   // [N, HID] fp16
    int N)
{
    __shared__ float sW[HID][32];  // transposed: sW[j][k] = W[k][j]
    for (int i = threadIdx.x; i < 32 * HID; i += 256) {
        int k = i / HID, j = i % HID;
        sW[j][k] = W[i];
    }
    __syncthreads();

    int idx = blockIdx.x * 256 + threadIdx.x;
    if (idx >= N) return;

    ull xp[16];
    {
        const float4* p4 = reinterpret_cast<const float4*>(h + (size_t)idx * DD);
        #pragma unroll
        for (int q = 0; q < 8; q++) {
            F4P u; u.v = p4[q];
            xp[2*q] = u.p[0]; xp[2*q+1] = u.p[1];
        }
    }

    float out[HID];
    #pragma unroll 4
    for (int j = 0; j < HID; j++) {
        const float4* w4 = reinterpret_cast<const float4*>(sW[j]);
        ull a0 = 0ull, a1 = 0ull;
        #pragma unroll
        for (int q = 0; q < 8; q++) {
            F4P w; w.v = w4[q];
            a0 = ffma2(xp[2*q],   w.p[0], a0);
            a1 = ffma2(xp[2*q+1], w.p[1], a1);
        }
        float x0, x1, y0, y1;
        funpack(a0, x0, x1); funpack(a1, y0, y1);
        out[j] = (x0 + y0) + (x1 + y1);
    }

    uint4* po = reinterpret_cast<uint4*>(P + (size_t)idx * HID);
    #pragma unroll
    for (int q = 0; q < 5; q++) {
        U4H u;
        #pragma unroll
        for (int k = 0; k < 4; k++)
            u.h[k] = __float22half2_rn(
                make_float2(out[q*8 + 2*k], out[q*8 + 2*k + 1]));
        po[q] = u.v;
    }
}

// ---------------------------------------------------------------------------
// Edge: hsum[b,ti,:] += relu(F[b,fi,:] + T[b,ti,:])   (all fp16)
// one thread per (b, e) edge instance
// ---------------------------------------------------------------------------
__global__ __launch_bounds__(256) void edge_kernel(
    const __half* __restrict__ F,        // [B*NUM_VN, HID]
    const __half* __restrict__ T,        // [B*NUM_CN, HID]
    const int*    __restrict__ from_ind, // [E]
    const int*    __restrict__ to_ind,   // [E]
    __half*       __restrict__ hsum)     // [B*NUM_CN, HID]
{
    int idx = blockIdx.x * 256 + threadIdx.x;   // [0, B*E)
    int e = idx & (EE - 1);
    int b = idx >> 18;

    int fi = from_ind[e];
    int ti = to_ind[e];

    const uint4* pf = reinterpret_cast<const uint4*>(
        F + ((size_t)b * NUM_VN + fi) * HID);
    const uint4* pt = reinterpret_cast<const uint4*>(
        T + ((size_t)b * NUM_CN + ti) * HID);

    U4H fa[5], ta[5];
    #pragma unroll
    for (int q = 0; q < 5; q++) fa[q].v = pf[q];
    #pragma unroll
    for (int q = 0; q < 5; q++) ta[q].v = pt[q];

    const __half2 z2 = __float2half2_rn(0.f);
    __half* base = hsum + ((size_t)b * NUM_CN + ti) * HID;

    #pragma unroll
    for (int q = 0; q < 5; q++) {
        U4H r;
        #pragma unroll
        for (int k = 0; k < 4; k++)
            r.h[k] = __hmax2(__hadd2(fa[q].h[k], ta[q].h[k]), z2);
        asm volatile(
            "red.global.add.noftz.v4.f16x2 [%0], {%1, %2, %3, %4};"
            :: "l"(base + q * 8), "r"(r.u[0]), "r"(r.u[1]),
               "r"(r.u[2]), "r"(r.u[3])
            : "memory");
    }
}

// ---------------------------------------------------------------------------
// m[n,:] = float(hsum[n,:]) @ Wm2   (40 -> 20)
// one thread per (b, cn) node
// ---------------------------------------------------------------------------
__global__ __launch_bounds__(256) void m_kernel(
    const __half* __restrict__ hsum,   // [B*NUM_CN, HID]
    const float*  __restrict__ Wm2,    // [HID, MSG]
    float*        __restrict__ m)      // [B*NUM_CN, MSG]
{
    __shared__ float sW2[HID][MSG];
    for (int i = threadIdx.x; i < HID * MSG; i += 256)
        (&sW2[0][0])[i] = Wm2[i];
    __syncthreads();

    int idx = blockIdx.x * 256 + threadIdx.x;   // [0, B*NUM_CN)

    const uint4* ph = reinterpret_cast<const uint4*>(hsum + (size_t)idx * HID);
    U4H hb[5];
    #pragma unroll
    for (int q = 0; q < 5; q++) hb[q].v = ph[q];

    ull acc[10];
    #pragma unroll
    for (int q = 0; q < 10; q++) acc[q] = 0ull;

    #pragma unroll 5
    for (int p = 0; p < 20; p++) {
        float2 hf = __half22float2(hb[p / 4].h[p % 4]);
        ull h0 = fpack(hf.x, hf.x);
        ull h1 = fpack(hf.y, hf.y);
        const float4* w0 = reinterpret_cast<const float4*>(sW2[2*p]);
        const float4* w1 = reinterpret_cast<const float4*>(sW2[2*p + 1]);
        #pragma unroll
        for (int q = 0; q < 5; q++) {
            F4P a; a.v = w0[q];
            F4P c; c.v = w1[q];
            acc[2*q]   = ffma2(h0, a.p[0], acc[2*q]);
            acc[2*q+1] = ffma2(h0, a.p[1], acc[2*q+1]);
            acc[2*q]   = ffma2(h1, c.p[0], acc[2*q]);
            acc[2*q+1] = ffma2(h1, c.p[1], acc[2*q+1]);
        }
    }

    float mv[MSG];
    #pragma unroll
    for (int q = 0; q < 10; q++) funpack(acc[q], mv[2*q], mv[2*q+1]);
    float4* po = reinterpret_cast<float4*>(m + (size_t)idx * MSG);
    #pragma unroll
    for (int q = 0; q < 5; q++)
        po[q] = make_float4(mv[4*q], mv[4*q+1], mv[4*q+2], mv[4*q+3]);
}

// ---------------------------------------------------------------------------
// Node: out = relu([m, h_to, logit] @ We1) @ We2
// one thread per (b, cn) node
// ---------------------------------------------------------------------------
__global__ __launch_bounds__(256) void node_kernel(
    const float* __restrict__ msum,   // [B*NUM_CN, MSG]
    const float* __restrict__ h_to,   // [B*NUM_CN, D]
    const float* __restrict__ logit,  // [B*NUM_CN]
    const float* __restrict__ We1,    // [53, HID]
    const float* __restrict__ We2,    // [HID, D]
    float*       __restrict__ out)    // [B*NUM_CN, D]
{
    __shared__ float sE1[HID][56];    // transposed, padded 53->56
    __shared__ float sE2[HID][DD];
    {
        for (int i = threadIdx.x; i < HID * 56; i += 256) {
            int j = i / 56, k = i % 56;
            sE1[j][k] = (k < MSG + DD + 1) ? We1[k * HID + j] : 0.f;
        }
        for (int i = threadIdx.x; i < HID * DD; i += 256)
            (&sE2[0][0])[i] = We2[i];
    }
    __syncthreads();

    int idx = blockIdx.x * 256 + threadIdx.x;   // [0, B*NUM_CN)

    ull ein[28];
    {
        const float4* pm = reinterpret_cast<const float4*>(msum + (size_t)idx * MSG);
        #pragma unroll
        for (int q = 0; q < 5; q++) {
            F4P u; u.v = pm[q];
            ein[2*q] = u.p[0]; ein[2*q+1] = u.p[1];
        }
        const float4* ph = reinterpret_cast<const float4*>(h_to + (size_t)idx * DD);
        #pragma unroll
        for (int q = 0; q < 8; q++) {
            F4P u; u.v = ph[q];
            ein[10+2*q] = u.p[0]; ein[10+2*q+1] = u.p[1];
        }
        ein[26] = fpack(logit[idx], 0.f);
        ein[27] = 0ull;
    }

    ull acc[16];
    #pragma unroll
    for (int q = 0; q < 16; q++) acc[q] = 0ull;

    #pragma unroll 4
    for (int j = 0; j < HID; j++) {
        const float4* w4 = reinterpret_cast<const float4*>(sE1[j]);
        ull a0 = 0ull, a1 = 0ull, a2 = 0ull, a3 = 0ull;
        #pragma unroll
        for (int q = 0; q < 12; q += 4) {
            F4P w0; w0.v = w4[q];
            F4P w1; w1.v = w4[q+1];
            F4P w2; w2.v = w4[q+2];
            F4P w3; w3.v = w4[q+3];
            a0 = ffma2(ein[2*q],   w0.p[0], a0);
            a1 = ffma2(ein[2*q+1], w0.p[1], a1);
            a2 = ffma2(ein[2*q+2], w1.p[0], a2);
            a3 = ffma2(ein[2*q+3], w1.p[1], a3);
            a0 = ffma2(ein[2*q+4], w2.p[0], a0);
            a1 = ffma2(ein[2*q+5], w2.p[1], a1);
            a2 = ffma2(ein[2*q+6], w3.p[0], a2);
            a3 = ffma2(ein[2*q+7], w3.p[1], a3);
        }
        {
            F4P w0; w0.v = w4[12];
            F4P w1; w1.v = w4[13];
            a0 = ffma2(ein[24], w0.p[0], a0);
            a1 = ffma2(ein[25], w0.p[1], a1);
            a2 = ffma2(ein[26], w1.p[0], a2);
            a3 = ffma2(ein[27], w1.p[1], a3);
        }
        float x0, x1, y0, y1, u0, u1, v0, v1;
        funpack(a0, x0, x1); funpack(a1, y0, y1);
        funpack(a2, u0, u1); funpack(a3, v0, v1);
        float hv = fmaxf(((x0 + y0) + (x1 + y1)) + ((u0 + v0) + (u1 + v1)), 0.f);
        ull hh = fpack(hv, hv);

        const float4* v4 = reinterpret_cast<const float4*>(sE2[j]);
        #pragma unroll
        for (int q = 0; q < 8; q++) {
            F4P w; w.v = v4[q];
            acc[2*q]   = ffma2(hh, w.p[0], acc[2*q]);
            acc[2*q+1] = ffma2(hh, w.p[1], acc[2*q+1]);
        }
    }

    float o[DD];
    #pragma unroll
    for (int q = 0; q < 16; q++) funpack(acc[q], o[2*q], o[2*q+1]);
    float4* po = reinterpret_cast<float4*>(out + (size_t)idx * DD);
    #pragma unroll
    for (int q = 0; q < 8; q++)
        po[q] = make_float4(o[4*q], o[4*q+1], o[4*q+2], o[4*q+3]);
}

// ---------------------------------------------------------------------------
static void run_side(const float* h_from, const float* h_to,
                     const float* logit,
                     const int* from_ind, const int* to_ind,
                     const float* Wm1, const float* Wm2,
                     const float* We1, const float* We2,
                     __half* F, __half* T, __half* HS, float* M, float* out)
{
    const int Nf = BB * NUM_VN;   // 262144
    const int Nt = BB * NUM_CN;   // 131072

    // zero hsum (fp16, 80B rows -> uint4 count)
    {
        const int n = (int)((size_t)Nt * HID * sizeof(__half) / 16);
        zero_kernel<<<(n + 255) / 256, 256>>>(
            reinterpret_cast<uint4*>(HS), n);
    }
    pre_kernel<<<Nf / 256, 256>>>(h_from, Wm1, F, Nf);
    pre_kernel<<<Nt / 256, 256>>>(h_to, Wm1 + 32 * HID, T, Nt);

    edge_kernel<<<(BB * EE) / 256, 256>>>(F, T, from_ind, to_ind, HS);

    m_kernel<<<Nt / 256, 256>>>(HS, Wm2, M);
    node_kernel<<<Nt / 256, 256>>>(M, h_to, logit, We1, We2, out);
}

extern "C" void kernel_launch(void* const* d_in, const int* in_sizes, int n_in,
                              void* d_out, int out_size) {
    const float* h_from     = (const float*)d_in[0];
    const float* h_to_x     = (const float*)d_in[1];
    const float* h_to_z     = (const float*)d_in[2];
    const float* hx_logit   = (const float*)d_in[3];
    const float* hz_logit   = (const float*)d_in[4];
    const int*   from_ind_x = (const int*)  d_in[5];
    const int*   to_ind_x   = (const int*)  d_in[6];
    const int*   from_ind_z = (const int*)  d_in[7];
    const int*   to_ind_z   = (const int*)  d_in[8];
    const float* Wm1_x      = (const float*)d_in[9];
    const float* Wm2_x      = (const float*)d_in[10];
    const float* Wm1_z      = (const float*)d_in[11];
    const float* Wm2_z      = (const float*)d_in[12];
    const float* We1_x      = (const float*)d_in[13];
    const float* We2_x      = (const float*)d_in[14];
    const float* We1_z      = (const float*)d_in[15];
    const float* We2_z      = (const float*)d_in[16];
    float* out = (float*)d_out;

    __half *F = nullptr, *T = nullptr, *HS = nullptr;
    float* M = nullptr;
    cudaGetSymbolAddress((void**)&F, g_Fh);
    cudaGetSymbolAddress((void**)&T, g_Th);
    cudaGetSymbolAddress((void**)&HS, g_hsum);
    cudaGetSymbolAddress((void**)&M, g_m);

    run_side(h_from, h_to_x, hx_logit, from_ind_x, to_ind_x,
             Wm1_x, Wm2_x, We1_x, We2_x, F, T, HS, M, out);
    run_side(h_from, h_to_z, hz_logit, from_ind_z, to_ind_z,
             Wm1_z, Wm2_z, We1_z, We2_z, F, T, HS, M,
             out + (size_t)BB * NUM_CN * DD);
}